// round 15
// baseline (speedup 1.0000x reference)
#include <cuda_runtime.h>
#include <cstdint>

// Problem constants (fixed shapes from the reference)
constexpr int T = 8;
constexpr int N = 200000;
constexpr int D = 128;        // embedding dim (fp32) -> 512 bytes/row
constexpr int B = 8192;       // bags per table (power of 2)
constexpr int L = 163840;     // indices per table
constexpr int D4 = D / 4;     // 32 float4 per row; one per lane

constexpr int GROUP = 4;      // rows per cp.async group
constexpr int RING  = 4;      // smem group slots (3 committed ahead — measured optimum)
constexpr int WARPS_PER_CTA = 2;
constexpr int CTAS_PER_SM   = 14;   // 16KB smem/CTA -> 28 warps/SM
                                    // live window = 4256 bags = 0.52 table

constexpr int CHUNK_LOG2 = 3;       // interleave grain 8 bags (was 64): cuts
                                    // inter-stream dispersion 2048 -> 256 bags,
                                    // shrinking the straddle window at table
                                    // transitions (the remaining traffic excess)
constexpr int CHUNK      = 1 << CHUNK_LOG2;

constexpr int TOTAL_BAGS      = T * B;                       // 65536
constexpr int NUM_STREAMS     = 32;
constexpr int BAGS_PER_STREAM = TOTAL_BAGS / NUM_STREAMS;    // 2048
constexpr int NUM_BLOCKS      = 152 * CTAS_PER_SM;           // 2128

// One padded counter per stream (own 128B line). Zero-initialized at module
// load; the LAST CTA to exit resets them (atomicExch, L2-native) for the next
// graph replay. NO __threadfence anywhere: gpu-scope fences emit CCTL.IVALL
// (full L1D flush); measured cost ~100 GB/s per 2128 flushes (R11/R13).
// Ordering is already guaranteed: each warp consumed the return value of its
// final g_ctr atomicAdd, so that atomic is performed at L2 before the warp
// reaches the exit path; cross-launch visibility comes from the kernel
// completion boundary that graph replay enforces.
struct __align__(128) StreamCtr { unsigned int v; unsigned int pad[31]; };
__device__ StreamCtr g_ctr[NUM_STREAMS];
__device__ unsigned int g_done;

__device__ __forceinline__ uint32_t smem_u32(const void* p) {
    uint32_t a;
    asm("{ .reg .u64 t; cvta.to.shared.u64 t, %1; cvt.u32.u64 %0, t; }"
        : "=r"(a) : "l"(p));
    return a;
}

__device__ __forceinline__ void cp_async16(uint32_t saddr, const void* gptr, int pred) {
    asm volatile(
        "{\n\t"
        ".reg .pred p;\n\t"
        "setp.ne.u32 p, %2, 0;\n\t"
        "@p cp.async.cg.shared.global [%0], [%1], 16;\n\t"
        "}"
        :: "r"(saddr), "l"(gptr), "r"((unsigned)pred) : "memory");
}

// Continuous-stream gather (measured-optimum structure):
// issue side walks bags (one bag prefetched ahead; atomic grab hidden);
// accumulate side trails 3 groups behind; pipeline never drains.
// Index loads via __ldg (L1 broadcast, ~39cyc — latency-critical, R10 lesson).
// meta pack: [g:17 | count:3 | last:1] -> (g<<4)|(count<<1)|last
__global__ __launch_bounds__(WARPS_PER_CTA * 32, CTAS_PER_SM)
void grouped_embedding_bag_kernel(const float* __restrict__ weights,   // [T, N, D]
                                  const int*   __restrict__ values,    // [T, L]
                                  const int*   __restrict__ offsets,   // [T, B+1]
                                  float*       __restrict__ out)       // [B, T*D]
{
    __shared__ float4 buf[WARPS_PER_CTA][RING * GROUP][32];   // 16 KB per CTA

    const int lane    = threadIdx.x & 31;
    const int warp_in = threadIdx.x >> 5;
    const int stream  = blockIdx.x & (NUM_STREAMS - 1);

    const uint32_t s_base = smem_u32(&buf[warp_in][0][lane]);
    const float4* __restrict__ w4 = reinterpret_cast<const float4*>(weights);
    float4* __restrict__ out4 = reinterpret_cast<float4*>(out);

    // ---- bag fetch (warp-collective; one bag of lookahead) ----
    int  cg = 0, ci = 0, cend = 0; bool chave = false;  // current bag
    int  ng = 0, ni = 0, nend = 0; bool nhave = false;  // next bag

    auto fetch_into = [&](int& g, int& i, int& e, bool& have) {
        unsigned int pos;
        if (lane == 0) pos = atomicAdd(&g_ctr[stream].v, 1u);
        pos = __shfl_sync(0xffffffffu, pos, 0);
        if (pos >= (unsigned)BAGS_PER_STREAM) { have = false; return; }
        const int chunk = (int)(pos >> CHUNK_LOG2);
        const int off   = (int)(pos & (CHUNK - 1));
        g = ((chunk * NUM_STREAMS + stream) << CHUNK_LOG2) + off;
        const int t = g >> 13;
        const int b = g & (B - 1);
        i = __ldg(&offsets[t * (B + 1) + b]);
        e = __ldg(&offsets[t * (B + 1) + b + 1]);
        have = true;
    };

    fetch_into(cg, ci, cend, chave);
    fetch_into(ng, ni, nend, nhave);

    // ---- issue one group into smem slot; returns meta ----
    auto issue_one = [&](int slot) -> unsigned int {
        unsigned int m = 0u;
        if (chave) {
            const int t = cg >> 13;
            const int* __restrict__ vals = values + (size_t)t * L;
            const float4* __restrict__ wt = w4 + (size_t)t * N * D4;
            const int count = min(GROUP, cend - ci);
            const bool last = (ci + count >= cend);
            #pragma unroll
            for (int j = 0; j < GROUP; ++j) {
                const int valid = (j < count);
                const int idx = valid ? __ldg(&vals[ci + j]) : 0;   // L1 broadcast
                cp_async16(s_base + (uint32_t)((slot * GROUP + j) * 32 * sizeof(float4)),
                           wt + (size_t)idx * D4 + lane, valid);
            }
            m = ((unsigned)cg << 4) | ((unsigned)count << 1) | (last ? 1u : 0u);
            ci += count;
            if (last) {
                cg = ng; ci = ni; cend = nend; chave = nhave;
                fetch_into(ng, ni, nend, nhave);
            }
        }
        asm volatile("cp.async.commit_group;" ::: "memory");
        return m;
    };

    float acc0 = 0.f, acc1 = 0.f, acc2 = 0.f, acc3 = 0.f;

    auto accumulate = [&](unsigned int m, int slot) {
        const int count = (int)((m >> 1) & 7u);
        #pragma unroll
        for (int j = 0; j < GROUP; ++j) {
            if (j < count) {
                float4 v = buf[warp_in][slot * GROUP + j][lane];
                acc0 += v.x; acc1 += v.y; acc2 += v.z; acc3 += v.w;
            }
        }
        if (m & 1u) {   // last group of its bag: flush
            const int g = (int)(m >> 4);
            const int t = g >> 13;
            const int b = g & (B - 1);
            __stcs(out4 + (size_t)b * (T * D4) + t * D4 + lane,
                   make_float4(acc0, acc1, acc2, acc3));
            acc0 = acc1 = acc2 = acc3 = 0.f;
        }
    };

    // ---- prime: 3 groups committed ahead (steady state) ----
    unsigned int meta_a = issue_one(0);
    unsigned int meta_b = issue_one(1);
    unsigned int meta_c = issue_one(2);
    int s_acc = 0, s_issue = 3;

    while (true) {
        asm volatile("cp.async.wait_group 2;" ::: "memory");   // oldest done
        accumulate(meta_a, s_acc);
        s_acc = (s_acc + 1) & (RING - 1);
        if (chave) {
            const unsigned int m = issue_one(s_issue);
            s_issue = (s_issue + 1) & (RING - 1);
            meta_a = meta_b; meta_b = meta_c; meta_c = m;
        } else {
            // drain the remaining two pending groups
            asm volatile("cp.async.wait_group 1;" ::: "memory");
            accumulate(meta_b, s_acc);
            s_acc = (s_acc + 1) & (RING - 1);
            asm volatile("cp.async.wait_group 0;" ::: "memory");
            accumulate(meta_c, s_acc);
            break;
        }
    }

    // ---- last CTA out resets counters for the next graph replay ----
    // One atomic per CTA; NO fences (see note above g_ctr declaration).
    __syncthreads();
    if (threadIdx.x == 0) {
        const unsigned int d = atomicAdd(&g_done, 1u) + 1u;
        if (d == (unsigned)NUM_BLOCKS) {
            #pragma unroll
            for (int s = 0; s < NUM_STREAMS; ++s) atomicExch(&g_ctr[s].v, 0u);
            atomicExch(&g_done, 0u);
        }
    }
}

extern "C" void kernel_launch(void* const* d_in, const int* in_sizes, int n_in,
                              void* d_out, int out_size)
{
    const float* weights = (const float*)d_in[0];   // [T, N, D] fp32
    const int*   values  = (const int*)d_in[1];     // [T, L] int32
    const int*   offsets = (const int*)d_in[2];     // [T, B+1] int32
    float*       out     = (float*)d_out;           // [B, T*D] fp32

    // One persistent wave: 14 CTAs/SM (16KB smem each) x 152 SMs = 28 warps/SM.
    // Stream counters are zero-initialized at module load and re-zeroed by the
    // last exiting CTA, so no separate reset launch is needed.
    grouped_embedding_bag_kernel<<<NUM_BLOCKS, WARPS_PER_CTA * 32>>>(
        weights, values, offsets, out);
}

// round 17
// speedup vs baseline: 1.1259x; 1.1259x over previous
#include <cuda_runtime.h>
#include <cstdint>

// Problem constants (fixed shapes from the reference)
constexpr int T = 8;
constexpr int N = 200000;
constexpr int D = 128;        // embedding dim (fp32) -> 512 bytes/row
constexpr int B = 8192;       // bags per table (power of 2)
constexpr int L = 163840;     // indices per table
constexpr int D4 = D / 4;     // 32 float4 per row; one per lane

constexpr int GROUP = 4;      // rows per cp.async group
constexpr int RING  = 4;      // smem group slots (3 committed ahead — measured optimum)
constexpr int WARPS_PER_CTA = 2;
constexpr int CTAS_PER_SM   = 14;   // 16KB smem/CTA -> 28 warps/SM
                                    // window = 4256 bags = 0.52 table (measured
                                    // traffic optimum across R7/R8/R9)

constexpr int CHUNK_LOG2 = 6;       // interleave grain 64 bags — measured optimum.
                                    // (8-bag grain cooled the index/offset L1
                                    // working set: -15% BW, R15)
constexpr int CHUNK      = 1 << CHUNK_LOG2;

constexpr int TOTAL_BAGS      = T * B;                       // 65536
constexpr int NUM_STREAMS     = 32;
constexpr int BAGS_PER_STREAM = TOTAL_BAGS / NUM_STREAMS;    // 2048
constexpr int NUM_BLOCKS      = 152 * CTAS_PER_SM;           // 2128

// One padded counter per stream (own 128B line). Zero-initialized at module
// load; the LAST CTA to exit resets them (atomicExch, L2-native) for the next
// graph replay. NO __threadfence anywhere: gpu-scope fences emit CCTL.IVALL
// (full L1D flush); measured cost ~100 GB/s per 2128 flushes (R11/R13).
// Ordering is already guaranteed: each warp consumed the return value of its
// final g_ctr atomicAdd, so that atomic is performed at L2 before the warp
// reaches the exit path; cross-launch visibility comes from the kernel
// completion boundary that graph replay enforces.
struct __align__(128) StreamCtr { unsigned int v; unsigned int pad[31]; };
__device__ StreamCtr g_ctr[NUM_STREAMS];
__device__ unsigned int g_done;

__device__ __forceinline__ uint32_t smem_u32(const void* p) {
    uint32_t a;
    asm("{ .reg .u64 t; cvta.to.shared.u64 t, %1; cvt.u32.u64 %0, t; }"
        : "=r"(a) : "l"(p));
    return a;
}

__device__ __forceinline__ void cp_async16(uint32_t saddr, const void* gptr, int pred) {
    asm volatile(
        "{\n\t"
        ".reg .pred p;\n\t"
        "setp.ne.u32 p, %2, 0;\n\t"
        "@p cp.async.cg.shared.global [%0], [%1], 16;\n\t"
        "}"
        :: "r"(saddr), "l"(gptr), "r"((unsigned)pred) : "memory");
}

// Continuous-stream gather (measured-optimum structure):
// issue side walks bags (one bag prefetched ahead; atomic grab hidden);
// accumulate side trails 3 groups behind; pipeline never drains.
// Index loads via __ldg (L1 broadcast, ~39cyc — latency-critical; both __ldcs
// (R10) and fine interleave (R15) that cooled this path cost ~15% BW).
// meta pack: [g:17 | count:3 | last:1] -> (g<<4)|(count<<1)|last
__global__ __launch_bounds__(WARPS_PER_CTA * 32, CTAS_PER_SM)
void grouped_embedding_bag_kernel(const float* __restrict__ weights,   // [T, N, D]
                                  const int*   __restrict__ values,    // [T, L]
                                  const int*   __restrict__ offsets,   // [T, B+1]
                                  float*       __restrict__ out)       // [B, T*D]
{
    __shared__ float4 buf[WARPS_PER_CTA][RING * GROUP][32];   // 16 KB per CTA

    const int lane    = threadIdx.x & 31;
    const int warp_in = threadIdx.x >> 5;
    const int stream  = blockIdx.x & (NUM_STREAMS - 1);

    const uint32_t s_base = smem_u32(&buf[warp_in][0][lane]);
    const float4* __restrict__ w4 = reinterpret_cast<const float4*>(weights);
    float4* __restrict__ out4 = reinterpret_cast<float4*>(out);

    // ---- bag fetch (warp-collective; one bag of lookahead) ----
    int  cg = 0, ci = 0, cend = 0; bool chave = false;  // current bag
    int  ng = 0, ni = 0, nend = 0; bool nhave = false;  // next bag

    auto fetch_into = [&](int& g, int& i, int& e, bool& have) {
        unsigned int pos;
        if (lane == 0) pos = atomicAdd(&g_ctr[stream].v, 1u);
        pos = __shfl_sync(0xffffffffu, pos, 0);
        if (pos >= (unsigned)BAGS_PER_STREAM) { have = false; return; }
        const int chunk = (int)(pos >> CHUNK_LOG2);
        const int off   = (int)(pos & (CHUNK - 1));
        g = ((chunk * NUM_STREAMS + stream) << CHUNK_LOG2) + off;
        const int t = g >> 13;
        const int b = g & (B - 1);
        i = __ldg(&offsets[t * (B + 1) + b]);
        e = __ldg(&offsets[t * (B + 1) + b + 1]);
        have = true;
    };

    fetch_into(cg, ci, cend, chave);
    fetch_into(ng, ni, nend, nhave);

    // ---- issue one group into smem slot; returns meta ----
    auto issue_one = [&](int slot) -> unsigned int {
        unsigned int m = 0u;
        if (chave) {
            const int t = cg >> 13;
            const int* __restrict__ vals = values + (size_t)t * L;
            const float4* __restrict__ wt = w4 + (size_t)t * N * D4;
            const int count = min(GROUP, cend - ci);
            const bool last = (ci + count >= cend);
            #pragma unroll
            for (int j = 0; j < GROUP; ++j) {
                const int valid = (j < count);
                const int idx = valid ? __ldg(&vals[ci + j]) : 0;   // L1 broadcast
                cp_async16(s_base + (uint32_t)((slot * GROUP + j) * 32 * sizeof(float4)),
                           wt + (size_t)idx * D4 + lane, valid);
            }
            m = ((unsigned)cg << 4) | ((unsigned)count << 1) | (last ? 1u : 0u);
            ci += count;
            if (last) {
                cg = ng; ci = ni; cend = nend; chave = nhave;
                fetch_into(ng, ni, nend, nhave);
            }
        }
        asm volatile("cp.async.commit_group;" ::: "memory");
        return m;
    };

    float acc0 = 0.f, acc1 = 0.f, acc2 = 0.f, acc3 = 0.f;

    auto accumulate = [&](unsigned int m, int slot) {
        const int count = (int)((m >> 1) & 7u);
        #pragma unroll
        for (int j = 0; j < GROUP; ++j) {
            if (j < count) {
                float4 v = buf[warp_in][slot * GROUP + j][lane];
                acc0 += v.x; acc1 += v.y; acc2 += v.z; acc3 += v.w;
            }
        }
        if (m & 1u) {   // last group of its bag: flush
            const int g = (int)(m >> 4);
            const int t = g >> 13;
            const int b = g & (B - 1);
            __stcs(out4 + (size_t)b * (T * D4) + t * D4 + lane,
                   make_float4(acc0, acc1, acc2, acc3));
            acc0 = acc1 = acc2 = acc3 = 0.f;
        }
    };

    // ---- prime: 3 groups committed ahead (steady state) ----
    unsigned int meta_a = issue_one(0);
    unsigned int meta_b = issue_one(1);
    unsigned int meta_c = issue_one(2);
    int s_acc = 0, s_issue = 3;

    while (true) {
        asm volatile("cp.async.wait_group 2;" ::: "memory");   // oldest done
        accumulate(meta_a, s_acc);
        s_acc = (s_acc + 1) & (RING - 1);
        if (chave) {
            const unsigned int m = issue_one(s_issue);
            s_issue = (s_issue + 1) & (RING - 1);
            meta_a = meta_b; meta_b = meta_c; meta_c = m;
        } else {
            // drain the remaining two pending groups
            asm volatile("cp.async.wait_group 1;" ::: "memory");
            accumulate(meta_b, s_acc);
            s_acc = (s_acc + 1) & (RING - 1);
            asm volatile("cp.async.wait_group 0;" ::: "memory");
            accumulate(meta_c, s_acc);
            break;
        }
    }

    // ---- last CTA out resets counters for the next graph replay ----
    // One atomic per CTA; NO fences (see note above g_ctr declaration).
    __syncthreads();
    if (threadIdx.x == 0) {
        const unsigned int d = atomicAdd(&g_done, 1u) + 1u;
        if (d == (unsigned)NUM_BLOCKS) {
            #pragma unroll
            for (int s = 0; s < NUM_STREAMS; ++s) atomicExch(&g_ctr[s].v, 0u);
            atomicExch(&g_done, 0u);
        }
    }
}

extern "C" void kernel_launch(void* const* d_in, const int* in_sizes, int n_in,
                              void* d_out, int out_size)
{
    const float* weights = (const float*)d_in[0];   // [T, N, D] fp32
    const int*   values  = (const int*)d_in[1];     // [T, L] int32
    const int*   offsets = (const int*)d_in[2];     // [T, B+1] int32
    float*       out     = (float*)d_out;           // [B, T*D] fp32

    // One persistent wave: 14 CTAs/SM (16KB smem each) x 152 SMs = 28 warps/SM.
    // Stream counters are zero-initialized at module load and re-zeroed by the
    // last exiting CTA, so no separate reset launch is needed.
    grouped_embedding_bag_kernel<<<NUM_BLOCKS, WARPS_PER_CTA * 32>>>(
        weights, values, offsets, out);
}